// round 5
// baseline (speedup 1.0000x reference)
#include <cuda_runtime.h>
#include <math.h>

#define D 128

// ---------------------------------------------------------------------------
// Scratch (device globals — zero-initialized at load; kernels restore the
// all-zero invariant every call, so NO memsets are needed at runtime).
// ---------------------------------------------------------------------------
#define MAXROWS 716800          // >= NE+NF+NA+NF+NE = 700000
__device__ float    g_agg[(size_t)MAXROWS * D];   // segment sums (self-zeroing)
__device__ float    g_cnt[MAXROWS];               // counts (self-zeroing)
__device__ unsigned g_B[5 * 2 * D * D];           // tf32 bits: [t][wl|wr][n][k]

// ---------------------------------------------------------------------------
// prep: convert all 5 wl / wr matrices to tf32 bits. Layout [t][side][n*128+k]
// ---------------------------------------------------------------------------
struct PrepParams { const float* wl[5]; const float* wr[5]; };

__global__ void prep_kernel(PrepParams p) {
    int i = blockIdx.x * blockDim.x + threadIdx.x;      // 0 .. 163839
    int t = i >> 15;
    int r = i & 32767;
    int side = r >> 14;
    int idx = r & 16383;
    float v = (side ? p.wr[t] : p.wl[t])[idx];
    unsigned u;
    asm("cvt.rna.tf32.f32 %0, %1;" : "=r"(u) : "f"(v));
    g_B[i] = u;
}

// ---------------------------------------------------------------------------
// Mega-scatter: one warp per edge across ALL 5 types. Each lane gathers a
// float4 of the source row and does one 128-bit global reduction.
// ---------------------------------------------------------------------------
struct ScatParams {
    const float* xs[5];
    const int*   si[5];
    const int*   di[5];
    size_t aggOff[5];     // in floats
    int    cntOff[5];     // in rows
    long long wPrefix[6]; // cumulative warp (=edge) counts
};

__global__ void scatter_kernel(ScatParams p) {
    long long gt = (long long)blockIdx.x * blockDim.x + threadIdx.x;
    long long w = gt >> 5;
    int c = (int)(gt & 31);
    if (w >= p.wPrefix[5]) return;
    int t = 0;
    while (w >= p.wPrefix[t + 1]) t++;
    int e = (int)(w - p.wPrefix[t]);

    int s = p.si[t][e];
    int d = p.di[t][e];
    float4 v = ((const float4*)(p.xs[t] + (size_t)s * D))[c];
    float* dst = g_agg + p.aggOff[t] + (size_t)d * D + c * 4;
    asm volatile("red.global.add.v4.f32 [%0], {%1,%2,%3,%4};"
                 :: "l"(dst), "f"(v.x), "f"(v.y), "f"(v.z), "f"(v.w)
                 : "memory");
    if (c == 0) atomicAdd(g_cnt + p.cntOff[t] + d, 1.0f);
}

// ---------------------------------------------------------------------------
// Mega-GEMM (tf32 mma.sync.m16n8k8), double-buffered smem pipeline:
//   C[M x 128] = [x_dst | agg/max(cnt,1)] (M x 256) @ [wl^T ; wr^T]
// then + bias, row L2-normalize. MODE 0: plain store. MODE 1: load+add+store.
// Reads of agg/cnt REZERO them in place (restores invariant for next replay).
// ---------------------------------------------------------------------------
__device__ __forceinline__ void mma_tf32(float* c, const unsigned* a,
                                         unsigned b0, unsigned b1) {
    asm volatile(
        "mma.sync.aligned.m16n8k8.row.col.f32.tf32.tf32.f32 "
        "{%0,%1,%2,%3}, {%4,%5,%6,%7}, {%8,%9}, {%0,%1,%2,%3};"
        : "+f"(c[0]), "+f"(c[1]), "+f"(c[2]), "+f"(c[3])
        : "r"(a[0]), "r"(a[1]), "r"(a[2]), "r"(a[3]), "r"(b0), "r"(b1));
}

struct GemmParams {
    const float* xd[5];
    const float* bias[5];
    float*       out[5];
    size_t aggOff[5];
    int    cntOff[5];
    int    tIdx[5];       // global type index (selects g_B slice)
    int    nd[5];
    int    blkPrefix[6];
};

#define TILE_WORDS (128 * 36)          // one As or Bs buffer

template <int MODE>
__global__ __launch_bounds__(256) void gemm_kernel(GemmParams p) {
    extern __shared__ unsigned smemRaw[];   // 2 * 2 * TILE_WORDS
    typedef unsigned Row36[36];

    int b = blockIdx.x;
    int t = 0;
    while (b >= p.blkPrefix[t + 1]) t++;
    int rowBase = (b - p.blkPrefix[t]) * 128;
    int n_dst = p.nd[t];
    const float* xd  = p.xd[t];
    float*       agg = g_agg + p.aggOff[t];
    float*       cnt = g_cnt + p.cntOff[t];
    const unsigned* Bl = g_B + (size_t)p.tIdx[t] * 32768;
    const unsigned* Br = Bl + 16384;

    __shared__ float rowsum[2][128];
    __shared__ float invc_s[128];

    int tid = threadIdx.x;
    int wid = tid >> 5, lane = tid & 31;
    int warpM = wid & 3, warpN = wid >> 2;
    int lq = lane & 3;
    int lr = lane >> 2;

    // read counts once, rezero in place
    if (tid < 128) {
        int gr = rowBase + tid;
        float cc = 1.0f;
        if (gr < n_dst) { cc = cnt[gr]; cnt[gr] = 0.0f; }
        invc_s[tid] = 1.0f / fmaxf(cc, 1.0f);
    }

    float acc[2][8][4];
#pragma unroll
    for (int mt = 0; mt < 2; mt++)
#pragma unroll
        for (int nt = 0; nt < 8; nt++)
#pragma unroll
            for (int r = 0; r < 4; r++) acc[mt][nt][r] = 0.f;

    float4 av[4];
    uint4  bv[4];

    // ---- tile fetch into registers (and agg rezero) ----
    auto loadRegs = [&](int kt) {
        bool isAgg = (kt >= 4);
        int kLocal = (kt & 3) * 32;
        const float* srcA = isAgg ? (const float*)agg : xd;
        const unsigned* Bp = isAgg ? Br : Bl;
#pragma unroll
        for (int it = 0; it < 4; it++) {
            int f = it * 256 + tid;
            int r = f >> 3;
            int c4 = (f & 7) * 4;
            int gr = rowBase + r;
            av[it] = make_float4(0.f, 0.f, 0.f, 0.f);
            if (gr < n_dst) {
                float* ap = (float*)(srcA + (size_t)gr * D + kLocal + c4);
                av[it] = *(const float4*)ap;
                if (isAgg)   // restore zero for next graph replay
                    *(float4*)ap = make_float4(0.f, 0.f, 0.f, 0.f);
            }
            bv[it] = *(const uint4*)(Bp + (size_t)r * D + kLocal + c4);
        }
    };
    // ---- convert + store tile to smem buffer ----
    auto cvtSts = [&](int buf, int kt) {
        bool isAgg = (kt >= 4);
        Row36* As = (Row36*)(smemRaw + buf * 2 * TILE_WORDS);
        Row36* Bs = As + 128;
#pragma unroll
        for (int it = 0; it < 4; it++) {
            int f = it * 256 + tid;
            int r = f >> 3;
            int c4 = (f & 7) * 4;
            float4 v = av[it];
            if (isAgg) {
                float s = invc_s[r];
                v.x *= s; v.y *= s; v.z *= s; v.w *= s;
            }
            unsigned u0, u1, u2, u3;
            asm("cvt.rna.tf32.f32 %0, %1;" : "=r"(u0) : "f"(v.x));
            asm("cvt.rna.tf32.f32 %0, %1;" : "=r"(u1) : "f"(v.y));
            asm("cvt.rna.tf32.f32 %0, %1;" : "=r"(u2) : "f"(v.z));
            asm("cvt.rna.tf32.f32 %0, %1;" : "=r"(u3) : "f"(v.w));
            As[r][c4 + 0] = u0; As[r][c4 + 1] = u1;
            As[r][c4 + 2] = u2; As[r][c4 + 3] = u3;
            uint4 u = bv[it];
            Bs[r][c4 + 0] = u.x; Bs[r][c4 + 1] = u.y;
            Bs[r][c4 + 2] = u.z; Bs[r][c4 + 3] = u.w;
        }
    };

    // prologue: tile 0
    loadRegs(0);
    cvtSts(0, 0);

    for (int kt = 0; kt < 8; kt++) {
        int buf = kt & 1;
        if (kt < 7) loadRegs(kt + 1);      // LDG issued before sync
        __syncthreads();                    // buf[kt&1] writes visible

        Row36* As = (Row36*)(smemRaw + buf * 2 * TILE_WORDS);
        Row36* Bs = As + 128;
#pragma unroll
        for (int k8 = 0; k8 < 4; k8++) {
            int kq = k8 * 8 + lq;
            unsigned a[2][4];
#pragma unroll
            for (int mt = 0; mt < 2; mt++) {
                int r0 = warpM * 32 + mt * 16 + lr;
                a[mt][0] = As[r0][kq];
                a[mt][1] = As[r0 + 8][kq];
                a[mt][2] = As[r0][kq + 4];
                a[mt][3] = As[r0 + 8][kq + 4];
            }
#pragma unroll
            for (int nt = 0; nt < 8; nt++) {
                int n0 = warpN * 64 + nt * 8 + lr;
                unsigned b0 = Bs[n0][kq];
                unsigned b1 = Bs[n0][kq + 4];
                mma_tf32(acc[0][nt], a[0], b0, b1);
                mma_tf32(acc[1][nt], a[1], b0, b1);
            }
        }
        if (kt < 7) cvtSts(buf ^ 1, kt + 1);
    }

    // ---- epilogue: bias, row L2-norm, store ----
    const float* bias = p.bias[t];
    float biasv[16];
#pragma unroll
    for (int nt = 0; nt < 8; nt++) {
        float2 bb = *(const float2*)(bias + warpN * 64 + nt * 8 + 2 * lq);
        biasv[2 * nt] = bb.x;
        biasv[2 * nt + 1] = bb.y;
    }

    float ps[2][2] = {{0.f, 0.f}, {0.f, 0.f}};
#pragma unroll
    for (int mt = 0; mt < 2; mt++)
#pragma unroll
        for (int nt = 0; nt < 8; nt++) {
            acc[mt][nt][0] += biasv[2 * nt];
            acc[mt][nt][1] += biasv[2 * nt + 1];
            acc[mt][nt][2] += biasv[2 * nt];
            acc[mt][nt][3] += biasv[2 * nt + 1];
            ps[mt][0] += acc[mt][nt][0] * acc[mt][nt][0]
                       + acc[mt][nt][1] * acc[mt][nt][1];
            ps[mt][1] += acc[mt][nt][2] * acc[mt][nt][2]
                       + acc[mt][nt][3] * acc[mt][nt][3];
        }
#pragma unroll
    for (int mt = 0; mt < 2; mt++)
#pragma unroll
        for (int h = 0; h < 2; h++) {
            float v = ps[mt][h];
            v += __shfl_xor_sync(0xffffffffu, v, 1);
            v += __shfl_xor_sync(0xffffffffu, v, 2);
            if (lq == 0)
                rowsum[warpN][warpM * 32 + mt * 16 + h * 8 + lr] = v;
        }
    __syncthreads();

    float* outp = p.out[t];
#pragma unroll
    for (int mt = 0; mt < 2; mt++)
#pragma unroll
        for (int h = 0; h < 2; h++) {
            int rloc = warpM * 32 + mt * 16 + h * 8 + lr;
            int gr = rowBase + rloc;
            if (gr >= n_dst) continue;
            float ss = rowsum[0][rloc] + rowsum[1][rloc];
            float inv = 1.f / fmaxf(sqrtf(ss), 1e-12f);
#pragma unroll
            for (int nt = 0; nt < 8; nt++) {
                float vx = acc[mt][nt][h * 2 + 0] * inv;
                float vy = acc[mt][nt][h * 2 + 1] * inv;
                float* pp = outp + (size_t)gr * D + warpN * 64 + nt * 8 + 2 * lq;
                if (MODE == 0) {
                    *(float2*)pp = make_float2(vx, vy);
                } else {
                    float2 old = *(const float2*)pp;
                    *(float2*)pp = make_float2(old.x + vx, old.y + vy);
                }
            }
        }
}

// ---------------------------------------------------------------------------
// Host orchestration — 4 launches: prep, scatter, gemm1, gemm2. No memsets
// (agg/cnt are self-zeroing; gemm1 plain-stores cover all of d_out).
// ---------------------------------------------------------------------------
extern "C" void kernel_launch(void* const* d_in, const int* in_sizes, int n_in,
                              void* d_out, int out_size) {
    const float* xa = (const float*)d_in[0];
    const float* xe = (const float*)d_in[1];
    const float* xf = (const float*)d_in[2];
    int NA = in_sizes[0] / D;
    int NE = in_sizes[1] / D;
    int NF = in_sizes[2] / D;

    float* out = (float*)d_out;
    float* out_a = out;
    float* out_e = out + (size_t)NA * D;
    float* out_f = out + (size_t)(NA + NE) * D;

    // EDGE_TYPES: (a->e), (a->f), (e->a), (e->f), (f->e)
    const float* xs[5] = {xa, xa, xe, xe, xf};
    const float* xd[5] = {xe, xf, xa, xf, xe};
    int nd[5]          = {NE, NF, NA, NF, NE};
    float* od[5]       = {out_e, out_f, out_a, out_f, out_e};

    PrepParams pp;
    ScatParams sp;

    size_t aggOffA[5];
    int cntOffA[5];
    int rowCum = 0;
    long long wCum = 0;
    sp.wPrefix[0] = 0;
    for (int t = 0; t < 5; t++) {
        pp.wl[t] = (const float*)d_in[13 + 3 * t];
        pp.wr[t] = (const float*)d_in[15 + 3 * t];
        sp.xs[t] = xs[t];
        sp.si[t] = (const int*)d_in[3 + 2 * t];
        sp.di[t] = (const int*)d_in[4 + 2 * t];
        sp.aggOff[t] = (size_t)rowCum * D;
        sp.cntOff[t] = rowCum;
        aggOffA[t] = (size_t)rowCum * D;
        cntOffA[t] = rowCum;
        rowCum += nd[t];
        wCum += in_sizes[3 + 2 * t];
        sp.wPrefix[t + 1] = wCum;
    }

    GemmParams g1, g2;
    int blk1 = 0, blk2 = 0;
    g1.blkPrefix[0] = 0; g2.blkPrefix[0] = 0;
    for (int i = 0; i < 3; i++) {
        int t = i;                        // types 0,1,2 -> plain store
        g1.xd[i] = xd[t];
        g1.bias[i] = (const float*)d_in[14 + 3 * t];
        g1.out[i] = od[t];
        g1.aggOff[i] = aggOffA[t];
        g1.cntOff[i] = cntOffA[t];
        g1.tIdx[i] = t;
        g1.nd[i] = nd[t];
        blk1 += (nd[t] + 127) / 128;
        g1.blkPrefix[i + 1] = blk1;
    }
    for (int i = 0; i < 2; i++) {
        int t = 3 + i;                    // types 3,4 -> load-add-store
        g2.xd[i] = xd[t];
        g2.bias[i] = (const float*)d_in[14 + 3 * t];
        g2.out[i] = od[t];
        g2.aggOff[i] = aggOffA[t];
        g2.cntOff[i] = cntOffA[t];
        g2.tIdx[i] = t;
        g2.nd[i] = nd[t];
        blk2 += (nd[t] + 127) / 128;
        g2.blkPrefix[i + 1] = blk2;
    }
    for (int i = 3; i < 5; i++) g1.blkPrefix[i + 1] = blk1;
    for (int i = 2; i < 5; i++) g2.blkPrefix[i + 1] = blk2;

    int smemBytes = 2 * 2 * TILE_WORDS * 4;   // 73728
    static bool attrSet = false;
    if (!attrSet) {
        cudaFuncSetAttribute(gemm_kernel<0>,
                             cudaFuncAttributeMaxDynamicSharedMemorySize, smemBytes);
        cudaFuncSetAttribute(gemm_kernel<1>,
                             cudaFuncAttributeMaxDynamicSharedMemorySize, smemBytes);
        attrSet = true;
    }

    prep_kernel<<<(5 * 2 * D * D) / 256, 256>>>(pp);

    long long thr = wCum * 32;
    int sblk = (int)((thr + 255) / 256);
    scatter_kernel<<<sblk, 256>>>(sp);

    gemm_kernel<0><<<blk1, 256, smemBytes>>>(g1);
    gemm_kernel<1><<<blk2, 256, smemBytes>>>(g2);
}

// round 6
// speedup vs baseline: 1.2052x; 1.2052x over previous
#include <cuda_runtime.h>
#include <cuda_fp16.h>
#include <math.h>

#define D 128

// ---------------------------------------------------------------------------
// Scratch (device globals — zero-init at load; kernels restore the all-zero
// invariant every call, so NO runtime memsets are needed).
// ---------------------------------------------------------------------------
#define MAXROWS 716800          // >= NE+NF+NA+NF+NE = 700000
__device__ float  g_agg[(size_t)MAXROWS * D];   // segment sums (self-zeroing)
__device__ float  g_cnt[MAXROWS];               // counts (self-zeroing)
__device__ __half g_Bh[5 * 2 * D * D];          // f16 weights: [t][wl|wr][n][k]

// ---------------------------------------------------------------------------
// prep: convert all 5 wl / wr matrices to f16. Layout [t][side][n*128+k]
// ---------------------------------------------------------------------------
struct PrepParams { const float* wl[5]; const float* wr[5]; };

__global__ void prep_kernel(PrepParams p) {
    int i = blockIdx.x * blockDim.x + threadIdx.x;      // 0 .. 163839
    int t = i >> 15;
    int r = i & 32767;
    int side = r >> 14;
    int idx = r & 16383;
    float v = (side ? p.wr[t] : p.wl[t])[idx];
    g_Bh[i] = __float2half_rn(v);
}

// ---------------------------------------------------------------------------
// Mega-scatter: one warp per edge across ALL 5 types (proven R2 design).
// ---------------------------------------------------------------------------
struct ScatParams {
    const float* xs[5];
    const int*   si[5];
    const int*   di[5];
    size_t aggOff[5];
    int    cntOff[5];
    long long wPrefix[6];
};

__global__ void scatter_kernel(ScatParams p) {
    long long gt = (long long)blockIdx.x * blockDim.x + threadIdx.x;
    long long w = gt >> 5;
    int c = (int)(gt & 31);
    if (w >= p.wPrefix[5]) return;
    int t = 0;
    while (w >= p.wPrefix[t + 1]) t++;
    int e = (int)(w - p.wPrefix[t]);

    int s = p.si[t][e];
    int d = p.di[t][e];
    float4 v = ((const float4*)(p.xs[t] + (size_t)s * D))[c];
    float* dst = g_agg + p.aggOff[t] + (size_t)d * D + c * 4;
    asm volatile("red.global.add.v4.f32 [%0], {%1,%2,%3,%4};"
                 :: "l"(dst), "f"(v.x), "f"(v.y), "f"(v.z), "f"(v.w)
                 : "memory");
    if (c == 0) atomicAdd(g_cnt + p.cntOff[t] + d, 1.0f);
}

// ---------------------------------------------------------------------------
// Mega-GEMM, fp16 mma.sync.m16n8k16 (fp32 accumulate), single-buffer, BK=64:
//   C[M x 128] = [x_dst | agg/max(cnt,1)] (M x 256) @ [wl^T ; wr^T]
// then + bias, row L2-normalize. MODE 0: plain store. MODE 1: load+add+store.
// agg/cnt reads REZERO in place (restores invariant for next graph replay).
// ---------------------------------------------------------------------------
__device__ __forceinline__ void mma_f16(float* c, const unsigned* a,
                                        unsigned b0, unsigned b1) {
    asm volatile(
        "mma.sync.aligned.m16n8k16.row.col.f32.f16.f16.f32 "
        "{%0,%1,%2,%3}, {%4,%5,%6,%7}, {%8,%9}, {%0,%1,%2,%3};"
        : "+f"(c[0]), "+f"(c[1]), "+f"(c[2]), "+f"(c[3])
        : "r"(a[0]), "r"(a[1]), "r"(a[2]), "r"(a[3]), "r"(b0), "r"(b1));
}

struct GemmParams {
    const float* xd[5];
    const float* bias[5];
    float*       out[5];
    size_t aggOff[5];
    int    cntOff[5];
    int    tIdx[5];
    int    nd[5];
    int    blkPrefix[6];
};

template <int MODE>
__global__ __launch_bounds__(256) void gemm_kernel(GemmParams p) {
    int b = blockIdx.x;
    int t = 0;
    while (b >= p.blkPrefix[t + 1]) t++;
    int rowBase = (b - p.blkPrefix[t]) * 128;
    int n_dst = p.nd[t];
    const float* xd  = p.xd[t];
    float*       agg = g_agg + p.aggOff[t];
    float*       cnt = g_cnt + p.cntOff[t];
    const __half* Bl = g_Bh + (size_t)p.tIdx[t] * 32768;   // wl [n][k]
    const __half* Br = Bl + 16384;                          // wr [n][k]

    // half2 words; [128][36] stride keeps all fragment LDS conflict-free
    __shared__ unsigned As[128][36];
    __shared__ unsigned Bs[128][36];
    __shared__ float rowsum[2][128];
    __shared__ float invc_s[128];

    int tid = threadIdx.x;
    int wid = tid >> 5, lane = tid & 31;
    int warpM = wid & 3, warpN = wid >> 2;
    int lq = lane & 3;        // thread-in-group
    int lr = lane >> 2;       // group row

    // counts: read once, rezero in place
    if (tid < 128) {
        int gr = rowBase + tid;
        float cc = 1.0f;
        if (gr < n_dst) { cc = cnt[gr]; cnt[gr] = 0.0f; }
        invc_s[tid] = 1.0f / fmaxf(cc, 1.0f);
    }

    float acc[2][8][4];
#pragma unroll
    for (int mt = 0; mt < 2; mt++)
#pragma unroll
        for (int nt = 0; nt < 8; nt++)
#pragma unroll
            for (int r = 0; r < 4; r++) acc[mt][nt][r] = 0.f;

    // K = 256 as 4 tiles of 64
    for (int kt = 0; kt < 4; kt++) {
        bool isAgg = (kt >= 2);
        int kLocal = (kt & 1) * 64;
        const float* srcA = isAgg ? (const float*)agg : xd;
        const __half* Bp  = isAgg ? Br : Bl;

        if (kt) __syncthreads();

        // A tile: 128 rows x 64 floats -> f16 half2 words [row][0..31]
#pragma unroll
        for (int it = 0; it < 8; it++) {
            int f = it * 256 + tid;        // 0..2047 float4 items
            int r = f >> 4;                // row
            int c16 = (f & 15);            // float4 index within 64-k
            int gr = rowBase + r;
            float4 v = make_float4(0.f, 0.f, 0.f, 0.f);
            if (gr < n_dst) {
                float* ap = (float*)(srcA + (size_t)gr * D + kLocal + c16 * 4);
                v = *(const float4*)ap;
                if (isAgg) {
                    *(float4*)ap = make_float4(0.f, 0.f, 0.f, 0.f);  // rezero
                    float s = invc_s[r];
                    v.x *= s; v.y *= s; v.z *= s; v.w *= s;
                }
            }
            __half2 lo = __floats2half2_rn(v.x, v.y);
            __half2 hi = __floats2half2_rn(v.z, v.w);
            As[r][c16 * 2 + 0] = *(unsigned*)&lo;
            As[r][c16 * 2 + 1] = *(unsigned*)&hi;
        }
        // B tile: 128 n-rows x 64 halfs (already f16) — uint4 copies
#pragma unroll
        for (int it = 0; it < 4; it++) {
            int f = it * 256 + tid;        // 0..1023 uint4 items
            int r = f >> 3;
            int w = (f & 7);
            uint4 u = *(const uint4*)(Bp + (size_t)r * D + kLocal + w * 8);
            *(uint4*)&Bs[r][w * 4] = u;
        }
        __syncthreads();

        // 4 k16 steps per 64-k tile
#pragma unroll
        for (int s = 0; s < 4; s++) {
            int k0 = s * 8 + lq;
            unsigned a[2][4];
#pragma unroll
            for (int mt = 0; mt < 2; mt++) {
                int r0 = warpM * 32 + mt * 16 + lr;
                a[mt][0] = As[r0][k0];
                a[mt][1] = As[r0 + 8][k0];
                a[mt][2] = As[r0][k0 + 4];
                a[mt][3] = As[r0 + 8][k0 + 4];
            }
#pragma unroll
            for (int nt = 0; nt < 8; nt++) {
                int n0 = warpN * 64 + nt * 8 + lr;
                unsigned b0 = Bs[n0][k0];
                unsigned b1 = Bs[n0][k0 + 4];
                mma_f16(acc[0][nt], a[0], b0, b1);
                mma_f16(acc[1][nt], a[1], b0, b1);
            }
        }
    }

    // ---- epilogue: bias, row L2-norm, store ----
    const float* bias = p.bias[t];
    float biasv[16];
#pragma unroll
    for (int nt = 0; nt < 8; nt++) {
        float2 bb = *(const float2*)(bias + warpN * 64 + nt * 8 + 2 * lq);
        biasv[2 * nt] = bb.x;
        biasv[2 * nt + 1] = bb.y;
    }

    float ps[2][2] = {{0.f, 0.f}, {0.f, 0.f}};
#pragma unroll
    for (int mt = 0; mt < 2; mt++)
#pragma unroll
        for (int nt = 0; nt < 8; nt++) {
            acc[mt][nt][0] += biasv[2 * nt];
            acc[mt][nt][1] += biasv[2 * nt + 1];
            acc[mt][nt][2] += biasv[2 * nt];
            acc[mt][nt][3] += biasv[2 * nt + 1];
            ps[mt][0] += acc[mt][nt][0] * acc[mt][nt][0]
                       + acc[mt][nt][1] * acc[mt][nt][1];
            ps[mt][1] += acc[mt][nt][2] * acc[mt][nt][2]
                       + acc[mt][nt][3] * acc[mt][nt][3];
        }
#pragma unroll
    for (int mt = 0; mt < 2; mt++)
#pragma unroll
        for (int h = 0; h < 2; h++) {
            float v = ps[mt][h];
            v += __shfl_xor_sync(0xffffffffu, v, 1);
            v += __shfl_xor_sync(0xffffffffu, v, 2);
            if (lq == 0)
                rowsum[warpN][warpM * 32 + mt * 16 + h * 8 + lr] = v;
        }
    __syncthreads();

    float* outp = p.out[t];
#pragma unroll
    for (int mt = 0; mt < 2; mt++)
#pragma unroll
        for (int h = 0; h < 2; h++) {
            int rloc = warpM * 32 + mt * 16 + h * 8 + lr;
            int gr = rowBase + rloc;
            if (gr >= n_dst) continue;
            float ss = rowsum[0][rloc] + rowsum[1][rloc];
            float inv = 1.f / fmaxf(sqrtf(ss), 1e-12f);
#pragma unroll
            for (int nt = 0; nt < 8; nt++) {
                float vx = acc[mt][nt][h * 2 + 0] * inv;
                float vy = acc[mt][nt][h * 2 + 1] * inv;
                float* pp = outp + (size_t)gr * D + warpN * 64 + nt * 8 + 2 * lq;
                if (MODE == 0) {
                    *(float2*)pp = make_float2(vx, vy);
                } else {
                    float2 old = *(const float2*)pp;
                    *(float2*)pp = make_float2(old.x + vx, old.y + vy);
                }
            }
        }
}

// ---------------------------------------------------------------------------
// Host orchestration — 4 launches: prep, scatter, gemm1, gemm2. No memsets.
// ---------------------------------------------------------------------------
extern "C" void kernel_launch(void* const* d_in, const int* in_sizes, int n_in,
                              void* d_out, int out_size) {
    const float* xa = (const float*)d_in[0];
    const float* xe = (const float*)d_in[1];
    const float* xf = (const float*)d_in[2];
    int NA = in_sizes[0] / D;
    int NE = in_sizes[1] / D;
    int NF = in_sizes[2] / D;

    float* out = (float*)d_out;
    float* out_a = out;
    float* out_e = out + (size_t)NA * D;
    float* out_f = out + (size_t)(NA + NE) * D;

    // EDGE_TYPES: (a->e), (a->f), (e->a), (e->f), (f->e)
    const float* xs[5] = {xa, xa, xe, xe, xf};
    const float* xd[5] = {xe, xf, xa, xf, xe};
    int nd[5]          = {NE, NF, NA, NF, NE};
    float* od[5]       = {out_e, out_f, out_a, out_f, out_e};

    PrepParams pp;
    ScatParams sp;

    size_t aggOffA[5];
    int cntOffA[5];
    int rowCum = 0;
    long long wCum = 0;
    sp.wPrefix[0] = 0;
    for (int t = 0; t < 5; t++) {
        pp.wl[t] = (const float*)d_in[13 + 3 * t];
        pp.wr[t] = (const float*)d_in[15 + 3 * t];
        sp.xs[t] = xs[t];
        sp.si[t] = (const int*)d_in[3 + 2 * t];
        sp.di[t] = (const int*)d_in[4 + 2 * t];
        sp.aggOff[t] = (size_t)rowCum * D;
        sp.cntOff[t] = rowCum;
        aggOffA[t] = (size_t)rowCum * D;
        cntOffA[t] = rowCum;
        rowCum += nd[t];
        wCum += in_sizes[3 + 2 * t];
        sp.wPrefix[t + 1] = wCum;
    }

    GemmParams g1, g2;
    int blk1 = 0, blk2 = 0;
    g1.blkPrefix[0] = 0; g2.blkPrefix[0] = 0;
    for (int i = 0; i < 3; i++) {
        int t = i;                        // types 0,1,2 -> plain store
        g1.xd[i] = xd[t];
        g1.bias[i] = (const float*)d_in[14 + 3 * t];
        g1.out[i] = od[t];
        g1.aggOff[i] = aggOffA[t];
        g1.cntOff[i] = cntOffA[t];
        g1.tIdx[i] = t;
        g1.nd[i] = nd[t];
        blk1 += (nd[t] + 127) / 128;
        g1.blkPrefix[i + 1] = blk1;
    }
    for (int i = 0; i < 2; i++) {
        int t = 3 + i;                    // types 3,4 -> load-add-store
        g2.xd[i] = xd[t];
        g2.bias[i] = (const float*)d_in[14 + 3 * t];
        g2.out[i] = od[t];
        g2.aggOff[i] = aggOffA[t];
        g2.cntOff[i] = cntOffA[t];
        g2.tIdx[i] = t;
        g2.nd[i] = nd[t];
        blk2 += (nd[t] + 127) / 128;
        g2.blkPrefix[i + 1] = blk2;
    }
    for (int i = 3; i < 5; i++) g1.blkPrefix[i + 1] = blk1;
    for (int i = 2; i < 5; i++) g2.blkPrefix[i + 1] = blk2;

    prep_kernel<<<(5 * 2 * D * D) / 256, 256>>>(pp);

    long long thr = wCum * 32;
    int sblk = (int)((thr + 255) / 256);
    scatter_kernel<<<sblk, 256>>>(sp);

    gemm_kernel<0><<<blk1, 256>>>(g1);
    gemm_kernel<1><<<blk2, 256>>>(g2);
}

// round 8
// speedup vs baseline: 2.4774x; 2.0556x over previous
#include <cuda_runtime.h>
#include <math.h>

#define D 128

// ---------------------------------------------------------------------------
// Scratch (device globals — zero-init at load; kernels restore the all-zero
// invariant every call, so NO runtime memsets are needed).
// ---------------------------------------------------------------------------
#define MAXROWS 716800          // >= NE+NF+NA+NF+NE = 700000 (slack covers tile overhang)
__device__ float    g_agg[(size_t)MAXROWS * D];   // segment sums (self-zeroing)
__device__ float    g_cnt[MAXROWS];               // counts (self-zeroing)
__device__ unsigned g_B[5 * 2 * D * D];           // tf32 bits: [t][wl|wr][n][k]

// ---------------------------------------------------------------------------
// prep: convert all 5 wl / wr matrices to tf32 bits. Layout [t][side][n*128+k]
// ---------------------------------------------------------------------------
struct PrepParams { const float* wl[5]; const float* wr[5]; };

__global__ void prep_kernel(PrepParams p) {
    int i = blockIdx.x * blockDim.x + threadIdx.x;      // 0 .. 163839
    int t = i >> 15;
    int r = i & 32767;
    int side = r >> 14;
    int idx = r & 16383;
    float v = (side ? p.wr[t] : p.wl[t])[idx];
    unsigned u;
    asm("cvt.rna.tf32.f32 %0, %1;" : "=r"(u) : "f"(v));
    g_B[i] = u;
}

// ---------------------------------------------------------------------------
// Mega-scatter: one warp per edge across ALL 5 types (proven R2 design).
// ---------------------------------------------------------------------------
struct ScatParams {
    const float* xs[5];
    const int*   si[5];
    const int*   di[5];
    size_t aggOff[5];
    int    cntOff[5];
    long long wPrefix[6];
};

__global__ void scatter_kernel(ScatParams p) {
    long long gt = (long long)blockIdx.x * blockDim.x + threadIdx.x;
    long long w = gt >> 5;
    int c = (int)(gt & 31);
    if (w >= p.wPrefix[5]) return;
    int t = 0;
    while (w >= p.wPrefix[t + 1]) t++;
    int e = (int)(w - p.wPrefix[t]);

    int s = p.si[t][e];
    int d = p.di[t][e];
    float4 v = ((const float4*)(p.xs[t] + (size_t)s * D))[c];
    float* dst = g_agg + p.aggOff[t] + (size_t)d * D + c * 4;
    asm volatile("red.global.add.v4.f32 [%0], {%1,%2,%3,%4};"
                 :: "l"(dst), "f"(v.x), "f"(v.y), "f"(v.z), "f"(v.w)
                 : "memory");
    if (c == 0) atomicAdd(g_cnt + p.cntOff[t] + d, 1.0f);
}

// ---------------------------------------------------------------------------
// Mega-GEMM, tf32 mma.sync.m16n8k8, cp.async 2-stage pipeline, BK=32.
// K-order: agg tiles (with wr) FIRST -> scale acc by 1/cnt -> xd tiles (wl).
// A fed as raw fp32 bits (tf32 truncation); B pre-rounded tf32.
// Epilogue: +bias, row L2-norm; MODE 0 plain store, MODE 1 load+add+store.
// agg/cnt rezeroed in place (restores invariant for next graph replay).
// ---------------------------------------------------------------------------
__device__ __forceinline__ void mma_tf32(float* c, const unsigned* a,
                                         unsigned b0, unsigned b1) {
    asm volatile(
        "mma.sync.aligned.m16n8k8.row.col.f32.tf32.tf32.f32 "
        "{%0,%1,%2,%3}, {%4,%5,%6,%7}, {%8,%9}, {%0,%1,%2,%3};"
        : "+f"(c[0]), "+f"(c[1]), "+f"(c[2]), "+f"(c[3])
        : "r"(a[0]), "r"(a[1]), "r"(a[2]), "r"(a[3]), "r"(b0), "r"(b1));
}

struct GemmParams {
    const float* xd[5];
    const float* bias[5];
    float*       out[5];
    size_t aggOff[5];
    int    cntOff[5];
    int    tIdx[5];
    int    nd[5];
    int    blkPrefix[6];
};

#define TILEW (128 * 36)     // words per As or Bs buffer (row stride 36 -> 144B, 16B-aligned)

template <int MODE>
__global__ __launch_bounds__(256) void gemm_kernel(GemmParams p) {
    extern __shared__ unsigned sm[];   // [As0 | As1 | Bs0 | Bs1], 4*TILEW words
    typedef unsigned Row36[36];

    int b = blockIdx.x;
    int t = 0;
    while (b >= p.blkPrefix[t + 1]) t++;
    int rowBase = (b - p.blkPrefix[t]) * 128;
    int n_dst = p.nd[t];
    const float* xd  = p.xd[t];
    float*       agg = g_agg + p.aggOff[t];
    float*       cnt = g_cnt + p.cntOff[t];
    const unsigned* Bl = g_B + (size_t)p.tIdx[t] * 32768;   // wl [n][k]
    const unsigned* Br = Bl + 16384;                         // wr [n][k]

    __shared__ float rowsum[2][128];
    __shared__ float invc_s[128];

    int tid = threadIdx.x;
    int wid = tid >> 5, lane = tid & 31;
    int warpM = wid & 3, warpN = wid >> 2;
    int lq = lane & 3;
    int lr = lane >> 2;

    unsigned smBase = (unsigned)__cvta_generic_to_shared(sm);

    // counts: read once, rezero in place
    if (tid < 128) {
        int gr = rowBase + tid;
        float cc = 1.0f;
        if (gr < n_dst) { cc = cnt[gr]; cnt[gr] = 0.0f; }
        invc_s[tid] = 1.0f / fmaxf(cc, 1.0f);
    }

    float acc[2][8][4];
#pragma unroll
    for (int mt = 0; mt < 2; mt++)
#pragma unroll
        for (int nt = 0; nt < 8; nt++)
#pragma unroll
            for (int r = 0; r < 4; r++) acc[mt][nt][r] = 0.f;

    // tile kt: kt<4 -> agg rows with wr; kt>=4 -> xd rows with wl
    auto issueTile = [&](int kt, int buf) {
        bool isAgg = (kt < 4);
        int kLocal = (kt & 3) * 32;
        const float* srcA = isAgg ? (const float*)agg : xd;
        const unsigned* Bp = isAgg ? Br : Bl;
        unsigned aBase = smBase + (unsigned)(buf * TILEW) * 4u;
        unsigned bBase = smBase + (unsigned)((2 + buf) * TILEW) * 4u;
#pragma unroll
        for (int it = 0; it < 4; it++) {
            int f = it * 256 + tid;       // 0..1023 16B chunks
            int r = f >> 3;
            int c4 = f & 7;
            int gr = rowBase + r;
            unsigned ad = aBase + (unsigned)(r * 36 + c4 * 4) * 4u;
            const float* asrc = srcA + (size_t)gr * D + kLocal + c4 * 4;
            int sz = (gr < n_dst) ? 16 : 0;     // OOB -> zero-fill
            asm volatile("cp.async.cg.shared.global [%0], [%1], 16, %2;"
                         :: "r"(ad), "l"(asrc), "r"(sz));
            unsigned bd = bBase + (unsigned)(r * 36 + c4 * 4) * 4u;
            const unsigned* bsrc = Bp + (size_t)r * D + kLocal + c4 * 4;
            asm volatile("cp.async.cg.shared.global [%0], [%1], 16;"
                         :: "r"(bd), "l"(bsrc));
        }
        asm volatile("cp.async.commit_group;" ::: "memory");
    };

    issueTile(0, 0);

    for (int kt = 0; kt < 8; kt++) {
        int buf = kt & 1;
        asm volatile("cp.async.wait_group 0;" ::: "memory");
        __syncthreads();                       // tile kt visible; prev mma done
        if (kt < 7) issueTile(kt + 1, buf ^ 1);   // overlaps with mma below

        Row36* As = (Row36*)(sm + buf * TILEW);
        Row36* Bs = (Row36*)(sm + (2 + buf) * TILEW);
#pragma unroll
        for (int k8 = 0; k8 < 4; k8++) {
            int kq = k8 * 8 + lq;
            unsigned a[2][4];
#pragma unroll
            for (int mt = 0; mt < 2; mt++) {
                int r0 = warpM * 32 + mt * 16 + lr;
                a[mt][0] = As[r0][kq];
                a[mt][1] = As[r0 + 8][kq];
                a[mt][2] = As[r0][kq + 4];
                a[mt][3] = As[r0 + 8][kq + 4];
            }
#pragma unroll
            for (int nt = 0; nt < 8; nt++) {
                int n0 = warpN * 64 + nt * 8 + lr;
                unsigned b0 = Bs[n0][kq];
                unsigned b1 = Bs[n0][kq + 4];
                mma_tf32(acc[0][nt], a[0], b0, b1);
                mma_tf32(acc[1][nt], a[1], b0, b1);
            }
        }

        if (kt == 3) {
            // finished agg@wr^T: scale by per-row 1/cnt, then xd@wl^T adds on top
#pragma unroll
            for (int mt = 0; mt < 2; mt++) {
                int r0 = warpM * 32 + mt * 16 + lr;
                float s0 = invc_s[r0];
                float s1 = invc_s[r0 + 8];
#pragma unroll
                for (int nt = 0; nt < 8; nt++) {
                    acc[mt][nt][0] *= s0; acc[mt][nt][1] *= s0;
                    acc[mt][nt][2] *= s1; acc[mt][nt][3] *= s1;
                }
            }
        }
    }

    // ---- rezero this block's agg rows: 128 rows x 128 cols = 4096 float4 ----
#pragma unroll
    for (int it = 0; it < 16; it++) {
        int f = it * 256 + tid;            // 0..4095 float4 chunks
        int r = f >> 5;                    // 0..127
        int c = f & 31;                    // 0..31 -> cols c*4 .. c*4+3
        int gr = rowBase + r;
        if (gr < n_dst)
            *(float4*)(agg + (size_t)gr * D + c * 4) =
                make_float4(0.f, 0.f, 0.f, 0.f);
    }

    // ---- epilogue: bias, row L2-norm, store ----
    const float* bias = p.bias[t];
    float biasv[16];
#pragma unroll
    for (int nt = 0; nt < 8; nt++) {
        float2 bb = *(const float2*)(bias + warpN * 64 + nt * 8 + 2 * lq);
        biasv[2 * nt] = bb.x;
        biasv[2 * nt + 1] = bb.y;
    }

    float ps[2][2] = {{0.f, 0.f}, {0.f, 0.f}};
#pragma unroll
    for (int mt = 0; mt < 2; mt++)
#pragma unroll
        for (int nt = 0; nt < 8; nt++) {
            acc[mt][nt][0] += biasv[2 * nt];
            acc[mt][nt][1] += biasv[2 * nt + 1];
            acc[mt][nt][2] += biasv[2 * nt];
            acc[mt][nt][3] += biasv[2 * nt + 1];
            ps[mt][0] += acc[mt][nt][0] * acc[mt][nt][0]
                       + acc[mt][nt][1] * acc[mt][nt][1];
            ps[mt][1] += acc[mt][nt][2] * acc[mt][nt][2]
                       + acc[mt][nt][3] * acc[mt][nt][3];
        }
#pragma unroll
    for (int mt = 0; mt < 2; mt++)
#pragma unroll
        for (int h = 0; h < 2; h++) {
            float v = ps[mt][h];
            v += __shfl_xor_sync(0xffffffffu, v, 1);
            v += __shfl_xor_sync(0xffffffffu, v, 2);
            if (lq == 0)
                rowsum[warpN][warpM * 32 + mt * 16 + h * 8 + lr] = v;
        }
    __syncthreads();

    float* outp = p.out[t];
#pragma unroll
    for (int mt = 0; mt < 2; mt++)
#pragma unroll
        for (int h = 0; h < 2; h++) {
            int rloc = warpM * 32 + mt * 16 + h * 8 + lr;
            int gr = rowBase + rloc;
            if (gr >= n_dst) continue;
            float ss = rowsum[0][rloc] + rowsum[1][rloc];
            float inv = 1.f / fmaxf(sqrtf(ss), 1e-12f);
#pragma unroll
            for (int nt = 0; nt < 8; nt++) {
                float vx = acc[mt][nt][h * 2 + 0] * inv;
                float vy = acc[mt][nt][h * 2 + 1] * inv;
                float* pp = outp + (size_t)gr * D + warpN * 64 + nt * 8 + 2 * lq;
                if (MODE == 0) {
                    *(float2*)pp = make_float2(vx, vy);
                } else {
                    float2 old = *(const float2*)pp;
                    *(float2*)pp = make_float2(old.x + vx, old.y + vy);
                }
            }
        }
}

// ---------------------------------------------------------------------------
// Host orchestration — 4 launches: prep, scatter, gemm1, gemm2. No memsets.
// ---------------------------------------------------------------------------
extern "C" void kernel_launch(void* const* d_in, const int* in_sizes, int n_in,
                              void* d_out, int out_size) {
    const float* xa = (const float*)d_in[0];
    const float* xe = (const float*)d_in[1];
    const float* xf = (const float*)d_in[2];
    int NA = in_sizes[0] / D;
    int NE = in_sizes[1] / D;
    int NF = in_sizes[2] / D;

    float* out = (float*)d_out;
    float* out_a = out;
    float* out_e = out + (size_t)NA * D;
    float* out_f = out + (size_t)(NA + NE) * D;

    // EDGE_TYPES: (a->e), (a->f), (e->a), (e->f), (f->e)
    const float* xs[5] = {xa, xa, xe, xe, xf};
    const float* xd[5] = {xe, xf, xa, xf, xe};
    int nd[5]          = {NE, NF, NA, NF, NE};
    float* od[5]       = {out_e, out_f, out_a, out_f, out_e};

    PrepParams pp;
    ScatParams sp;

    size_t aggOffA[5];
    int cntOffA[5];
    int rowCum = 0;
    long long wCum = 0;
    sp.wPrefix[0] = 0;
    for (int t = 0; t < 5; t++) {
        pp.wl[t] = (const float*)d_in[13 + 3 * t];
        pp.wr[t] = (const float*)d_in[15 + 3 * t];
        sp.xs[t] = xs[t];
        sp.si[t] = (const int*)d_in[3 + 2 * t];
        sp.di[t] = (const int*)d_in[4 + 2 * t];
        sp.aggOff[t] = (size_t)rowCum * D;
        sp.cntOff[t] = rowCum;
        aggOffA[t] = (size_t)rowCum * D;
        cntOffA[t] = rowCum;
        rowCum += nd[t];
        wCum += in_sizes[3 + 2 * t];
        sp.wPrefix[t + 1] = wCum;
    }

    GemmParams g1, g2;
    int blk1 = 0, blk2 = 0;
    g1.blkPrefix[0] = 0; g2.blkPrefix[0] = 0;
    for (int i = 0; i < 3; i++) {
        int t = i;                        // types 0,1,2 -> plain store
        g1.xd[i] = xd[t];
        g1.bias[i] = (const float*)d_in[14 + 3 * t];
        g1.out[i] = od[t];
        g1.aggOff[i] = aggOffA[t];
        g1.cntOff[i] = cntOffA[t];
        g1.tIdx[i] = t;
        g1.nd[i] = nd[t];
        blk1 += (nd[t] + 127) / 128;
        g1.blkPrefix[i + 1] = blk1;
    }
    for (int i = 0; i < 2; i++) {
        int t = 3 + i;                    // types 3,4 -> load-add-store
        g2.xd[i] = xd[t];
        g2.bias[i] = (const float*)d_in[14 + 3 * t];
        g2.out[i] = od[t];
        g2.aggOff[i] = aggOffA[t];
        g2.cntOff[i] = cntOffA[t];
        g2.tIdx[i] = t;
        g2.nd[i] = nd[t];
        blk2 += (nd[t] + 127) / 128;
        g2.blkPrefix[i + 1] = blk2;
    }
    for (int i = 3; i < 5; i++) g1.blkPrefix[i + 1] = blk1;
    for (int i = 2; i < 5; i++) g2.blkPrefix[i + 1] = blk2;

    int smemBytes = 4 * TILEW * 4;        // 73728
    cudaFuncSetAttribute(gemm_kernel<0>,
                         cudaFuncAttributeMaxDynamicSharedMemorySize, smemBytes);
    cudaFuncSetAttribute(gemm_kernel<1>,
                         cudaFuncAttributeMaxDynamicSharedMemorySize, smemBytes);

    prep_kernel<<<(5 * 2 * D * D) / 256, 256>>>(pp);

    long long thr = wCum * 32;
    int sblk = (int)((thr + 255) / 256);
    scatter_kernel<<<sblk, 256>>>(sp);

    gemm_kernel<0><<<blk1, 256, smemBytes>>>(g1);
    gemm_kernel<1><<<blk2, 256, smemBytes>>>(g2);
}

// round 9
// speedup vs baseline: 2.6018x; 1.0502x over previous
#include <cuda_runtime.h>
#include <math.h>

#define D 128

// ---------------------------------------------------------------------------
// Scratch (device globals — zero-init at load; kernels restore the all-zero
// invariant every call, so NO runtime memsets are needed).
// ---------------------------------------------------------------------------
#define MAXROWS 716800          // >= NE+NF+NA+NF+NE = 700000
__device__ float    g_agg[(size_t)MAXROWS * D];   // segment sums (self-zeroing)
__device__ float    g_cnt[MAXROWS];               // counts (self-zeroing)
__device__ unsigned g_B[5 * 2 * D * D];           // tf32 bits: [t][wl|wr][n][k]

// ---------------------------------------------------------------------------
// prep: convert all 5 wl / wr matrices to tf32 bits. Layout [t][side][n*128+k]
// ---------------------------------------------------------------------------
struct PrepParams { const float* wl[5]; const float* wr[5]; };

__global__ void prep_kernel(PrepParams p) {
    int i = blockIdx.x * blockDim.x + threadIdx.x;      // 0 .. 163839
    int t = i >> 15;
    int r = i & 32767;
    int side = r >> 14;
    int idx = r & 16383;
    float v = (side ? p.wr[t] : p.wl[t])[idx];
    unsigned u;
    asm("cvt.rna.tf32.f32 %0, %1;" : "=r"(u) : "f"(v));
    g_B[i] = u;
}

// ---------------------------------------------------------------------------
// Mega-scatter: one warp per edge across ALL 5 types (proven R2 design).
// ---------------------------------------------------------------------------
struct ScatParams {
    const float* xs[5];
    const int*   si[5];
    const int*   di[5];
    size_t aggOff[5];
    int    cntOff[5];
    long long wPrefix[6];
};

__global__ void scatter_kernel(ScatParams p) {
    long long gt = (long long)blockIdx.x * blockDim.x + threadIdx.x;
    long long w = gt >> 5;
    int c = (int)(gt & 31);
    if (w >= p.wPrefix[5]) return;
    int t = 0;
    while (w >= p.wPrefix[t + 1]) t++;
    int e = (int)(w - p.wPrefix[t]);

    int s = p.si[t][e];
    int d = p.di[t][e];
    float4 v = ((const float4*)(p.xs[t] + (size_t)s * D))[c];
    float* dst = g_agg + p.aggOff[t] + (size_t)d * D + c * 4;
    asm volatile("red.global.add.v4.f32 [%0], {%1,%2,%3,%4};"
                 :: "l"(dst), "f"(v.x), "f"(v.y), "f"(v.z), "f"(v.w)
                 : "memory");
    if (c == 0) atomicAdd(g_cnt + p.cntOff[t] + d, 1.0f);
}

// ---------------------------------------------------------------------------
// Mega-GEMM, tf32 mma.sync.m16n8k8, cp.async 3-STAGE pipeline, BK=32.
// wait_group 1 keeps two tiles in flight -> sustained DRAM MLP.
// K-order: agg tiles (with wr) FIRST -> scale acc by 1/cnt -> xd tiles (wl).
// Epilogue: +bias, row L2-norm; MODE 0 plain store, MODE 1 load+add+store.
// agg/cnt rezeroed in place (restores invariant for next graph replay).
// ---------------------------------------------------------------------------
__device__ __forceinline__ void mma_tf32(float* c, const unsigned* a,
                                         unsigned b0, unsigned b1) {
    asm volatile(
        "mma.sync.aligned.m16n8k8.row.col.f32.tf32.tf32.f32 "
        "{%0,%1,%2,%3}, {%4,%5,%6,%7}, {%8,%9}, {%0,%1,%2,%3};"
        : "+f"(c[0]), "+f"(c[1]), "+f"(c[2]), "+f"(c[3])
        : "r"(a[0]), "r"(a[1]), "r"(a[2]), "r"(a[3]), "r"(b0), "r"(b1));
}

struct GemmParams {
    const float* xd[5];
    const float* bias[5];
    float*       out[5];
    size_t aggOff[5];
    int    cntOff[5];
    int    tIdx[5];
    int    nd[5];
    int    blkPrefix[6];
};

#define TILEW (128 * 36)     // words per As or Bs buffer (stride 36 -> 144B, 16B-aligned)
#define STAGES 3

template <int MODE>
__global__ __launch_bounds__(256) void gemm_kernel(GemmParams p) {
    extern __shared__ unsigned sm[];   // STAGES * [As | Bs]
    typedef unsigned Row36[36];

    int b = blockIdx.x;
    int t = 0;
    while (b >= p.blkPrefix[t + 1]) t++;
    int rowBase = (b - p.blkPrefix[t]) * 128;
    int n_dst = p.nd[t];
    const float* xd  = p.xd[t];
    float*       agg = g_agg + p.aggOff[t];
    float*       cnt = g_cnt + p.cntOff[t];
    const unsigned* Bl = g_B + (size_t)p.tIdx[t] * 32768;   // wl [n][k]
    const unsigned* Br = Bl + 16384;                         // wr [n][k]

    __shared__ float rowsum[2][128];
    __shared__ float invc_s[128];

    int tid = threadIdx.x;
    int wid = tid >> 5, lane = tid & 31;
    int warpM = wid & 3, warpN = wid >> 2;
    int lq = lane & 3;
    int lr = lane >> 2;

    unsigned smBase = (unsigned)__cvta_generic_to_shared(sm);

    // counts: read once, rezero in place
    if (tid < 128) {
        int gr = rowBase + tid;
        float cc = 1.0f;
        if (gr < n_dst) { cc = cnt[gr]; cnt[gr] = 0.0f; }
        invc_s[tid] = 1.0f / fmaxf(cc, 1.0f);
    }

    float acc[2][8][4];
#pragma unroll
    for (int mt = 0; mt < 2; mt++)
#pragma unroll
        for (int nt = 0; nt < 8; nt++)
#pragma unroll
            for (int r = 0; r < 4; r++) acc[mt][nt][r] = 0.f;

    // tile kt: kt<4 -> agg rows with wr; kt>=4 -> xd rows with wl
    auto issueTile = [&](int kt, int buf) {
        bool isAgg = (kt < 4);
        int kLocal = (kt & 3) * 32;
        const float* srcA = isAgg ? (const float*)agg : xd;
        const unsigned* Bp = isAgg ? Br : Bl;
        unsigned aBase = smBase + (unsigned)(buf * 2 * TILEW) * 4u;
        unsigned bBase = aBase + (unsigned)TILEW * 4u;
#pragma unroll
        for (int it = 0; it < 4; it++) {
            int f = it * 256 + tid;       // 0..1023 16B chunks
            int r = f >> 3;
            int c4 = f & 7;
            int gr = rowBase + r;
            unsigned ad = aBase + (unsigned)(r * 36 + c4 * 4) * 4u;
            const float* asrc = srcA + (size_t)gr * D + kLocal + c4 * 4;
            int sz = (gr < n_dst) ? 16 : 0;     // OOB -> zero-fill
            asm volatile("cp.async.cg.shared.global [%0], [%1], 16, %2;"
                         :: "r"(ad), "l"(asrc), "r"(sz));
            unsigned bd = bBase + (unsigned)(r * 36 + c4 * 4) * 4u;
            const unsigned* bsrc = Bp + (size_t)r * D + kLocal + c4 * 4;
            asm volatile("cp.async.cg.shared.global [%0], [%1], 16;"
                         :: "r"(bd), "l"(bsrc));
        }
        asm volatile("cp.async.commit_group;" ::: "memory");
    };

    issueTile(0, 0);
    issueTile(1, 1);

    for (int kt = 0; kt < 8; kt++) {
        int buf = kt % STAGES;
        if (kt < 7)
            asm volatile("cp.async.wait_group 1;" ::: "memory");  // tile kt ready
        else
            asm volatile("cp.async.wait_group 0;" ::: "memory");
        __syncthreads();          // tile kt visible; mma on buf's prior tile done
        if (kt < 6) issueTile(kt + 2, (kt + 2) % STAGES);   // overlaps mma below

        Row36* As = (Row36*)(sm + buf * 2 * TILEW);
        Row36* Bs = As + 128;
#pragma unroll
        for (int k8 = 0; k8 < 4; k8++) {
            int kq = k8 * 8 + lq;
            unsigned a[2][4];
#pragma unroll
            for (int mt = 0; mt < 2; mt++) {
                int r0 = warpM * 32 + mt * 16 + lr;
                a[mt][0] = As[r0][kq];
                a[mt][1] = As[r0 + 8][kq];
                a[mt][2] = As[r0][kq + 4];
                a[mt][3] = As[r0 + 8][kq + 4];
            }
#pragma unroll
            for (int nt = 0; nt < 8; nt++) {
                int n0 = warpN * 64 + nt * 8 + lr;
                unsigned b0 = Bs[n0][kq];
                unsigned b1 = Bs[n0][kq + 4];
                mma_tf32(acc[0][nt], a[0], b0, b1);
                mma_tf32(acc[1][nt], a[1], b0, b1);
            }
        }

        if (kt == 3) {
            // finished agg@wr^T: scale by per-row 1/cnt; xd@wl^T adds on top
#pragma unroll
            for (int mt = 0; mt < 2; mt++) {
                int r0 = warpM * 32 + mt * 16 + lr;
                float s0 = invc_s[r0];
                float s1 = invc_s[r0 + 8];
#pragma unroll
                for (int nt = 0; nt < 8; nt++) {
                    acc[mt][nt][0] *= s0; acc[mt][nt][1] *= s0;
                    acc[mt][nt][2] *= s1; acc[mt][nt][3] *= s1;
                }
            }
        }
    }

    // ---- rezero this block's agg rows: 128 rows x 128 cols = 4096 float4 ----
#pragma unroll
    for (int it = 0; it < 16; it++) {
        int f = it * 256 + tid;            // 0..4095 float4 chunks
        int r = f >> 5;
        int c = f & 31;
        int gr = rowBase + r;
        if (gr < n_dst)
            *(float4*)(agg + (size_t)gr * D + c * 4) =
                make_float4(0.f, 0.f, 0.f, 0.f);
    }

    // ---- epilogue: bias, row L2-norm, store ----
    const float* bias = p.bias[t];
    float biasv[16];
#pragma unroll
    for (int nt = 0; nt < 8; nt++) {
        float2 bb = *(const float2*)(bias + warpN * 64 + nt * 8 + 2 * lq);
        biasv[2 * nt] = bb.x;
        biasv[2 * nt + 1] = bb.y;
    }

    float ps[2][2] = {{0.f, 0.f}, {0.f, 0.f}};
#pragma unroll
    for (int mt = 0; mt < 2; mt++)
#pragma unroll
        for (int nt = 0; nt < 8; nt++) {
            acc[mt][nt][0] += biasv[2 * nt];
            acc[mt][nt][1] += biasv[2 * nt + 1];
            acc[mt][nt][2] += biasv[2 * nt];
            acc[mt][nt][3] += biasv[2 * nt + 1];
            ps[mt][0] += acc[mt][nt][0] * acc[mt][nt][0]
                       + acc[mt][nt][1] * acc[mt][nt][1];
            ps[mt][1] += acc[mt][nt][2] * acc[mt][nt][2]
                       + acc[mt][nt][3] * acc[mt][nt][3];
        }
#pragma unroll
    for (int mt = 0; mt < 2; mt++)
#pragma unroll
        for (int h = 0; h < 2; h++) {
            float v = ps[mt][h];
            v += __shfl_xor_sync(0xffffffffu, v, 1);
            v += __shfl_xor_sync(0xffffffffu, v, 2);
            if (lq == 0)
                rowsum[warpN][warpM * 32 + mt * 16 + h * 8 + lr] = v;
        }
    __syncthreads();

    float* outp = p.out[t];
#pragma unroll
    for (int mt = 0; mt < 2; mt++)
#pragma unroll
        for (int h = 0; h < 2; h++) {
            int rloc = warpM * 32 + mt * 16 + h * 8 + lr;
            int gr = rowBase + rloc;
            if (gr >= n_dst) continue;
            float ss = rowsum[0][rloc] + rowsum[1][rloc];
            float inv = 1.f / fmaxf(sqrtf(ss), 1e-12f);
#pragma unroll
            for (int nt = 0; nt < 8; nt++) {
                float vx = acc[mt][nt][h * 2 + 0] * inv;
                float vy = acc[mt][nt][h * 2 + 1] * inv;
                float* pp = outp + (size_t)gr * D + warpN * 64 + nt * 8 + 2 * lq;
                if (MODE == 0) {
                    *(float2*)pp = make_float2(vx, vy);
                } else {
                    float2 old = *(const float2*)pp;
                    *(float2*)pp = make_float2(old.x + vx, old.y + vy);
                }
            }
        }
}

// ---------------------------------------------------------------------------
// Host orchestration — 4 launches: prep, scatter, gemm1, gemm2. No memsets.
// ---------------------------------------------------------------------------
extern "C" void kernel_launch(void* const* d_in, const int* in_sizes, int n_in,
                              void* d_out, int out_size) {
    const float* xa = (const float*)d_in[0];
    const float* xe = (const float*)d_in[1];
    const float* xf = (const float*)d_in[2];
    int NA = in_sizes[0] / D;
    int NE = in_sizes[1] / D;
    int NF = in_sizes[2] / D;

    float* out = (float*)d_out;
    float* out_a = out;
    float* out_e = out + (size_t)NA * D;
    float* out_f = out + (size_t)(NA + NE) * D;

    // EDGE_TYPES: (a->e), (a->f), (e->a), (e->f), (f->e)
    const float* xs[5] = {xa, xa, xe, xe, xf};
    const float* xd[5] = {xe, xf, xa, xf, xe};
    int nd[5]          = {NE, NF, NA, NF, NE};
    float* od[5]       = {out_e, out_f, out_a, out_f, out_e};

    PrepParams pp;
    ScatParams sp;

    size_t aggOffA[5];
    int cntOffA[5];
    int rowCum = 0;
    long long wCum = 0;
    sp.wPrefix[0] = 0;
    for (int t = 0; t < 5; t++) {
        pp.wl[t] = (const float*)d_in[13 + 3 * t];
        pp.wr[t] = (const float*)d_in[15 + 3 * t];
        sp.xs[t] = xs[t];
        sp.si[t] = (const int*)d_in[3 + 2 * t];
        sp.di[t] = (const int*)d_in[4 + 2 * t];
        sp.aggOff[t] = (size_t)rowCum * D;
        sp.cntOff[t] = rowCum;
        aggOffA[t] = (size_t)rowCum * D;
        cntOffA[t] = rowCum;
        rowCum += nd[t];
        wCum += in_sizes[3 + 2 * t];
        sp.wPrefix[t + 1] = wCum;
    }

    GemmParams g1, g2;
    int blk1 = 0, blk2 = 0;
    g1.blkPrefix[0] = 0; g2.blkPrefix[0] = 0;
    for (int i = 0; i < 3; i++) {
        int t = i;                        // types 0,1,2 -> plain store
        g1.xd[i] = xd[t];
        g1.bias[i] = (const float*)d_in[14 + 3 * t];
        g1.out[i] = od[t];
        g1.aggOff[i] = aggOffA[t];
        g1.cntOff[i] = cntOffA[t];
        g1.tIdx[i] = t;
        g1.nd[i] = nd[t];
        blk1 += (nd[t] + 127) / 128;
        g1.blkPrefix[i + 1] = blk1;
    }
    for (int i = 0; i < 2; i++) {
        int t = 3 + i;                    // types 3,4 -> load-add-store
        g2.xd[i] = xd[t];
        g2.bias[i] = (const float*)d_in[14 + 3 * t];
        g2.out[i] = od[t];
        g2.aggOff[i] = aggOffA[t];
        g2.cntOff[i] = cntOffA[t];
        g2.tIdx[i] = t;
        g2.nd[i] = nd[t];
        blk2 += (nd[t] + 127) / 128;
        g2.blkPrefix[i + 1] = blk2;
    }
    for (int i = 3; i < 5; i++) g1.blkPrefix[i + 1] = blk1;
    for (int i = 2; i < 5; i++) g2.blkPrefix[i + 1] = blk2;

    int smemBytes = STAGES * 2 * TILEW * 4;      // 110592
    cudaFuncSetAttribute(gemm_kernel<0>,
                         cudaFuncAttributeMaxDynamicSharedMemorySize, smemBytes);
    cudaFuncSetAttribute(gemm_kernel<1>,
                         cudaFuncAttributeMaxDynamicSharedMemorySize, smemBytes);

    prep_kernel<<<(5 * 2 * D * D) / 256, 256>>>(pp);

    long long thr = wCum * 32;
    int sblk = (int)((thr + 255) / 256);
    scatter_kernel<<<sblk, 256>>>(sp);

    gemm_kernel<0><<<blk1, 256, smemBytes>>>(g1);
    gemm_kernel<1><<<blk2, 256, smemBytes>>>(g2);
}

// round 10
// speedup vs baseline: 2.6982x; 1.0371x over previous
#include <cuda_runtime.h>
#include <math.h>

#define D 128

// ---------------------------------------------------------------------------
// Scratch (device globals — zero-init at load; kernels restore the all-zero
// invariant every call, so NO runtime memsets are needed).
// ---------------------------------------------------------------------------
#define MAXROWS 716800          // >= NE+NF+NA+NF+NE = 700000
__device__ float    g_agg[(size_t)MAXROWS * D];   // segment sums (self-zeroing)
__device__ float    g_cnt[MAXROWS];               // counts (self-zeroing)
__device__ unsigned g_B[5 * 2 * D * D];           // tf32 bits: [t][wl|wr][n][k]

// ---------------------------------------------------------------------------
// prep: convert all 5 wl / wr matrices to tf32 bits. Layout [t][side][n*128+k]
// ---------------------------------------------------------------------------
struct PrepParams { const float* wl[5]; const float* wr[5]; };

__global__ void prep_kernel(PrepParams p) {
    int i = blockIdx.x * blockDim.x + threadIdx.x;      // 0 .. 163839
    int t = i >> 15;
    int r = i & 32767;
    int side = r >> 14;
    int idx = r & 16383;
    float v = (side ? p.wr[t] : p.wl[t])[idx];
    unsigned u;
    asm("cvt.rna.tf32.f32 %0, %1;" : "=r"(u) : "f"(v));
    g_B[i] = u;
}

// ---------------------------------------------------------------------------
// Mega-scatter: one warp per edge across ALL 5 types (proven R2 design).
// ---------------------------------------------------------------------------
struct ScatParams {
    const float* xs[5];
    const int*   si[5];
    const int*   di[5];
    size_t aggOff[5];
    int    cntOff[5];
    long long wPrefix[6];
};

__global__ void scatter_kernel(ScatParams p) {
    long long gt = (long long)blockIdx.x * blockDim.x + threadIdx.x;
    long long w = gt >> 5;
    int c = (int)(gt & 31);
    if (w >= p.wPrefix[5]) return;
    int t = 0;
    while (w >= p.wPrefix[t + 1]) t++;
    int e = (int)(w - p.wPrefix[t]);

    int s = p.si[t][e];
    int d = p.di[t][e];
    float4 v = ((const float4*)(p.xs[t] + (size_t)s * D))[c];
    float* dst = g_agg + p.aggOff[t] + (size_t)d * D + c * 4;
    asm volatile("red.global.add.v4.f32 [%0], {%1,%2,%3,%4};"
                 :: "l"(dst), "f"(v.x), "f"(v.y), "f"(v.z), "f"(v.w)
                 : "memory");
    if (c == 0) atomicAdd(g_cnt + p.cntOff[t] + d, 1.0f);
}

// ---------------------------------------------------------------------------
// FUSED Mega-GEMM, tf32 mma.sync.m16n8k8, cp.async 3-stage pipeline, BK=32.
// One block owns 128 rows of ONE node-type segment and runs 1-2 passes:
//   pass 0: plain store; pass 1: load-add-store (L2-hot, same block's rows).
// Per pass: K-order agg tiles (wr) first -> scale by 1/cnt -> xd tiles (wl);
// then +bias, row L2-norm. agg/cnt rezeroed in place per pass.
// ---------------------------------------------------------------------------
__device__ __forceinline__ void mma_tf32(float* c, const unsigned* a,
                                         unsigned b0, unsigned b1) {
    asm volatile(
        "mma.sync.aligned.m16n8k8.row.col.f32.tf32.tf32.f32 "
        "{%0,%1,%2,%3}, {%4,%5,%6,%7}, {%8,%9}, {%0,%1,%2,%3};"
        : "+f"(c[0]), "+f"(c[1]), "+f"(c[2]), "+f"(c[3])
        : "r"(a[0]), "r"(a[1]), "r"(a[2]), "r"(a[3]), "r"(b0), "r"(b1));
}

struct GemmParams {
    const float* xd[3];          // dst-node features per segment
    float*       out[3];
    int          nd[3];
    int          npass[3];
    int          blkPrefix[4];
    const float* bias[3][2];
    size_t       aggOff[3][2];
    int          cntOff[3][2];
    int          tIdx[3][2];
};

#define TILEW (128 * 36)     // words per As or Bs buffer (stride 36 -> 144B)
#define STAGES 3

__global__ __launch_bounds__(256, 2) void gemm_kernel(GemmParams p) {
    extern __shared__ unsigned sm[];   // STAGES * [As | Bs]
    typedef unsigned Row36[36];

    int b = blockIdx.x;
    int seg = (b >= p.blkPrefix[1]) + (b >= p.blkPrefix[2]);
    int rowBase = (b - p.blkPrefix[seg]) * 128;
    int n_dst = p.nd[seg];
    const float* xd = p.xd[seg];
    float* outp = p.out[seg];
    int npass = p.npass[seg];

    __shared__ float rowsum[2][128];
    __shared__ float invc_s[128];

    int tid = threadIdx.x;
    int wid = tid >> 5, lane = tid & 31;
    int warpM = wid & 3, warpN = wid >> 2;
    int lq = lane & 3;
    int lr = lane >> 2;

    unsigned smBase = (unsigned)__cvta_generic_to_shared(sm);

    for (int pass = 0; pass < npass; pass++) {
        float* agg = g_agg + p.aggOff[seg][pass];
        float* cnt = g_cnt + p.cntOff[seg][pass];
        const unsigned* Bl = g_B + (size_t)p.tIdx[seg][pass] * 32768;  // wl
        const unsigned* Br = Bl + 16384;                               // wr

        // counts: read once, rezero in place
        if (tid < 128) {
            int gr = rowBase + tid;
            float cc = 1.0f;
            if (gr < n_dst) { cc = cnt[gr]; cnt[gr] = 0.0f; }
            invc_s[tid] = 1.0f / fmaxf(cc, 1.0f);
        }

        float acc[2][8][4];
#pragma unroll
        for (int mt = 0; mt < 2; mt++)
#pragma unroll
            for (int nt = 0; nt < 8; nt++)
#pragma unroll
                for (int r = 0; r < 4; r++) acc[mt][nt][r] = 0.f;

        // tile kt: kt<4 -> agg rows with wr; kt>=4 -> xd rows with wl
        auto issueTile = [&](int kt, int buf) {
            bool isAgg = (kt < 4);
            int kLocal = (kt & 3) * 32;
            const float* srcA = isAgg ? (const float*)agg : xd;
            const unsigned* Bp = isAgg ? Br : Bl;
            unsigned aBase = smBase + (unsigned)(buf * 2 * TILEW) * 4u;
            unsigned bBase = aBase + (unsigned)TILEW * 4u;
#pragma unroll
            for (int it = 0; it < 4; it++) {
                int f = it * 256 + tid;       // 0..1023 16B chunks
                int r = f >> 3;
                int c4 = f & 7;
                int gr = rowBase + r;
                unsigned ad = aBase + (unsigned)(r * 36 + c4 * 4) * 4u;
                const float* asrc = srcA + (size_t)gr * D + kLocal + c4 * 4;
                int sz = (gr < n_dst) ? 16 : 0;     // OOB -> zero-fill
                asm volatile("cp.async.cg.shared.global [%0], [%1], 16, %2;"
                             :: "r"(ad), "l"(asrc), "r"(sz));
                unsigned bd = bBase + (unsigned)(r * 36 + c4 * 4) * 4u;
                const unsigned* bsrc = Bp + (size_t)r * D + kLocal + c4 * 4;
                asm volatile("cp.async.cg.shared.global [%0], [%1], 16;"
                             :: "r"(bd), "l"(bsrc));
            }
            asm volatile("cp.async.commit_group;" ::: "memory");
        };

        issueTile(0, 0);
        issueTile(1, 1);

        for (int kt = 0; kt < 8; kt++) {
            int buf = kt % STAGES;
            if (kt < 7)
                asm volatile("cp.async.wait_group 1;" ::: "memory");
            else
                asm volatile("cp.async.wait_group 0;" ::: "memory");
            __syncthreads();      // tile kt visible; mma on buf's prior tile done
            if (kt < 6) issueTile(kt + 2, (kt + 2) % STAGES);

            Row36* As = (Row36*)(sm + buf * 2 * TILEW);
            Row36* Bs = As + 128;
#pragma unroll
            for (int k8 = 0; k8 < 4; k8++) {
                int kq = k8 * 8 + lq;
                unsigned a[2][4];
#pragma unroll
                for (int mt = 0; mt < 2; mt++) {
                    int r0 = warpM * 32 + mt * 16 + lr;
                    a[mt][0] = As[r0][kq];
                    a[mt][1] = As[r0 + 8][kq];
                    a[mt][2] = As[r0][kq + 4];
                    a[mt][3] = As[r0 + 8][kq + 4];
                }
#pragma unroll
                for (int nt = 0; nt < 8; nt++) {
                    int n0 = warpN * 64 + nt * 8 + lr;
                    unsigned b0 = Bs[n0][kq];
                    unsigned b1 = Bs[n0][kq + 4];
                    mma_tf32(acc[0][nt], a[0], b0, b1);
                    mma_tf32(acc[1][nt], a[1], b0, b1);
                }
            }

            if (kt == 3) {
                // finished agg@wr^T: scale by 1/cnt; xd@wl^T adds on top
#pragma unroll
                for (int mt = 0; mt < 2; mt++) {
                    int r0 = warpM * 32 + mt * 16 + lr;
                    float s0 = invc_s[r0];
                    float s1 = invc_s[r0 + 8];
#pragma unroll
                    for (int nt = 0; nt < 8; nt++) {
                        acc[mt][nt][0] *= s0; acc[mt][nt][1] *= s0;
                        acc[mt][nt][2] *= s1; acc[mt][nt][3] *= s1;
                    }
                }
            }
        }

        // ---- rezero this pass's agg rows: 128 x 128 = 4096 float4 ----
#pragma unroll
        for (int it = 0; it < 16; it++) {
            int f = it * 256 + tid;
            int r = f >> 5;
            int c = f & 31;
            int gr = rowBase + r;
            if (gr < n_dst)
                *(float4*)(agg + (size_t)gr * D + c * 4) =
                    make_float4(0.f, 0.f, 0.f, 0.f);
        }

        // ---- epilogue: bias, row L2-norm, store ----
        const float* bias = p.bias[seg][pass];
        float biasv[16];
#pragma unroll
        for (int nt = 0; nt < 8; nt++) {
            float2 bb = *(const float2*)(bias + warpN * 64 + nt * 8 + 2 * lq);
            biasv[2 * nt] = bb.x;
            biasv[2 * nt + 1] = bb.y;
        }

        float ps[2][2] = {{0.f, 0.f}, {0.f, 0.f}};
#pragma unroll
        for (int mt = 0; mt < 2; mt++)
#pragma unroll
            for (int nt = 0; nt < 8; nt++) {
                acc[mt][nt][0] += biasv[2 * nt];
                acc[mt][nt][1] += biasv[2 * nt + 1];
                acc[mt][nt][2] += biasv[2 * nt];
                acc[mt][nt][3] += biasv[2 * nt + 1];
                ps[mt][0] += acc[mt][nt][0] * acc[mt][nt][0]
                           + acc[mt][nt][1] * acc[mt][nt][1];
                ps[mt][1] += acc[mt][nt][2] * acc[mt][nt][2]
                           + acc[mt][nt][3] * acc[mt][nt][3];
            }
#pragma unroll
        for (int mt = 0; mt < 2; mt++)
#pragma unroll
            for (int h = 0; h < 2; h++) {
                float v = ps[mt][h];
                v += __shfl_xor_sync(0xffffffffu, v, 1);
                v += __shfl_xor_sync(0xffffffffu, v, 2);
                if (lq == 0)
                    rowsum[warpN][warpM * 32 + mt * 16 + h * 8 + lr] = v;
            }
        __syncthreads();

#pragma unroll
        for (int mt = 0; mt < 2; mt++)
#pragma unroll
            for (int h = 0; h < 2; h++) {
                int rloc = warpM * 32 + mt * 16 + h * 8 + lr;
                int gr = rowBase + rloc;
                if (gr >= n_dst) continue;
                float ss = rowsum[0][rloc] + rowsum[1][rloc];
                float inv = 1.f / fmaxf(sqrtf(ss), 1e-12f);
#pragma unroll
                for (int nt = 0; nt < 8; nt++) {
                    float vx = acc[mt][nt][h * 2 + 0] * inv;
                    float vy = acc[mt][nt][h * 2 + 1] * inv;
                    float* pp = outp + (size_t)gr * D + warpN * 64 + nt * 8 + 2 * lq;
                    if (pass == 0) {
                        *(float2*)pp = make_float2(vx, vy);
                    } else {
                        float2 old = *(const float2*)pp;   // L2-hot (own rows)
                        *(float2*)pp = make_float2(old.x + vx, old.y + vy);
                    }
                }
            }
    }
}

// ---------------------------------------------------------------------------
// Host orchestration — 3 launches: prep, scatter, fused gemm. No memsets.
// ---------------------------------------------------------------------------
extern "C" void kernel_launch(void* const* d_in, const int* in_sizes, int n_in,
                              void* d_out, int out_size) {
    const float* xa = (const float*)d_in[0];
    const float* xe = (const float*)d_in[1];
    const float* xf = (const float*)d_in[2];
    int NA = in_sizes[0] / D;
    int NE = in_sizes[1] / D;
    int NF = in_sizes[2] / D;

    float* out = (float*)d_out;
    float* out_a = out;
    float* out_e = out + (size_t)NA * D;
    float* out_f = out + (size_t)(NA + NE) * D;

    // EDGE_TYPES: (a->e), (a->f), (e->a), (e->f), (f->e)
    const float* xs[5] = {xa, xa, xe, xe, xf};
    int nd_t[5]        = {NE, NF, NA, NF, NE};

    PrepParams pp;
    ScatParams sp;

    size_t aggOffA[5];
    int cntOffA[5];
    int rowCum = 0;
    long long wCum = 0;
    sp.wPrefix[0] = 0;
    for (int t = 0; t < 5; t++) {
        pp.wl[t] = (const float*)d_in[13 + 3 * t];
        pp.wr[t] = (const float*)d_in[15 + 3 * t];
        sp.xs[t] = xs[t];
        sp.si[t] = (const int*)d_in[3 + 2 * t];
        sp.di[t] = (const int*)d_in[4 + 2 * t];
        sp.aggOff[t] = (size_t)rowCum * D;
        sp.cntOff[t] = rowCum;
        aggOffA[t] = (size_t)rowCum * D;
        cntOffA[t] = rowCum;
        rowCum += nd_t[t];
        wCum += in_sizes[3 + 2 * t];
        sp.wPrefix[t + 1] = wCum;
    }

    // Fused GEMM segments. Order: entity (2-pass), fact (2-pass), article
    // (1-pass) — long blocks first for a tight tail.
    GemmParams gp;
    // seg 0: entity — types {0, 4}
    gp.xd[0] = xe;  gp.out[0] = out_e;  gp.nd[0] = NE;  gp.npass[0] = 2;
    gp.tIdx[0][0] = 0; gp.tIdx[0][1] = 4;
    // seg 1: fact — types {1, 3}
    gp.xd[1] = xf;  gp.out[1] = out_f;  gp.nd[1] = NF;  gp.npass[1] = 2;
    gp.tIdx[1][0] = 1; gp.tIdx[1][1] = 3;
    // seg 2: article — type {2}
    gp.xd[2] = xa;  gp.out[2] = out_a;  gp.nd[2] = NA;  gp.npass[2] = 1;
    gp.tIdx[2][0] = 2; gp.tIdx[2][1] = 2;
    for (int s = 0; s < 3; s++)
        for (int q = 0; q < 2; q++) {
            int t = gp.tIdx[s][q];
            gp.aggOff[s][q] = aggOffA[t];
            gp.cntOff[s][q] = cntOffA[t];
            gp.bias[s][q] = (const float*)d_in[14 + 3 * t];
        }
    int bE = (NE + 127) / 128;
    int bF = (NF + 127) / 128;
    int bA = (NA + 127) / 128;
    gp.blkPrefix[0] = 0;
    gp.blkPrefix[1] = bE;
    gp.blkPrefix[2] = bE + bF;
    gp.blkPrefix[3] = bE + bF + bA;

    int smemBytes = STAGES * 2 * TILEW * 4;      // 110592
    cudaFuncSetAttribute(gemm_kernel,
                         cudaFuncAttributeMaxDynamicSharedMemorySize, smemBytes);

    prep_kernel<<<(5 * 2 * D * D) / 256, 256>>>(pp);

    long long thr = wCum * 32;
    int sblk = (int)((thr + 255) / 256);
    scatter_kernel<<<sblk, 256>>>(sp);

    gemm_kernel<<<gp.blkPrefix[3], 256, smemBytes>>>(gp);
}